// round 3
// baseline (speedup 1.0000x reference)
#include <cuda_runtime.h>
#include <cuda_bf16.h>
#include <stdint.h>

#define TLEN  512
#define BATCH 64
#define EMBD  512
#define HD    512
#define NG    2048
#define LT    48
#define MR    (TLEN*BATCH)   // 32768

// ---------------- device scratch (static globals, no allocation) ------------
__device__ __nv_bfloat16 g_A  [(size_t)MR*EMBD];     // gathered embeddings, m = t*64+b
__device__ __nv_bfloat16 g_Wih[(size_t)2*NG*EMBD];   // [dir*2048+r][k]
__device__ __nv_bfloat16 g_Whh[(size_t)2*NG*HD];
__device__ float         g_bias[2*NG];
__device__ __nv_bfloat16 g_fcw[(size_t)128*1024];    // fc_w padded to 128 rows
__device__ float         g_G  [(size_t)2*MR*NG];     // input gates + bias
__device__ __nv_bfloat16 g_H  [(size_t)2*MR*HD];     // hidden states
__device__ float         g_em [(size_t)MR*LT];       // emissions
__device__ float         g_llh[BATCH];
__device__ int           g_cnt[2];

// ---------------- helpers ----------------------------------------------------
__device__ __forceinline__ void cp_async16(void* smem, const void* gmem) {
    uint32_t s = (uint32_t)__cvta_generic_to_shared(smem);
    asm volatile("cp.async.cg.shared.global [%0], [%1], 16;\n" :: "r"(s), "l"(gmem));
}
__device__ __forceinline__ void cp_commit() { asm volatile("cp.async.commit_group;\n"); }
__device__ __forceinline__ void cp_wait0()  { asm volatile("cp.async.wait_group 0;\n"); }
__device__ __forceinline__ void cp_wait1()  { asm volatile("cp.async.wait_group 1;\n"); }

__device__ __forceinline__ void mma16816(float* c, const uint32_t* a, const uint32_t* b) {
    asm volatile("mma.sync.aligned.m16n8k16.row.col.f32.bf16.bf16.f32 "
                 "{%0,%1,%2,%3},{%4,%5,%6,%7},{%8,%9},{%0,%1,%2,%3};\n"
                 : "+f"(c[0]), "+f"(c[1]), "+f"(c[2]), "+f"(c[3])
                 : "r"(a[0]), "r"(a[1]), "r"(a[2]), "r"(a[3]), "r"(b[0]), "r"(b[1]));
}
__device__ __forceinline__ float tanh_f(float x) {
    float y; asm("tanh.approx.f32 %0, %1;" : "=f"(y) : "f"(x)); return y;
}
__device__ __forceinline__ float sig_f(float x) { return 1.f / (1.f + __expf(-x)); }

// ---------------- kernels ----------------------------------------------------
__global__ void k_reset() { if (threadIdx.x < 2) g_cnt[threadIdx.x] = 0; }

__global__ void k_prep(const float* wihf, const float* whhf, const float* bihf,
                       const float* bhhf, const float* wihb, const float* whhb,
                       const float* bihb, const float* bhhb, const float* fcw) {
    int id = blockIdx.x * blockDim.x + threadIdx.x;
    int st = gridDim.x * blockDim.x;
    const int NW = NG * EMBD;
    for (int i = id; i < NW; i += st) {
        g_Wih[i]      = __float2bfloat16(wihf[i]);
        g_Wih[NW + i] = __float2bfloat16(wihb[i]);
        g_Whh[i]      = __float2bfloat16(whhf[i]);
        g_Whh[NW + i] = __float2bfloat16(whhb[i]);
    }
    for (int i = id; i < NG; i += st) {
        g_bias[i]      = bihf[i] + bhhf[i];
        g_bias[NG + i] = bihb[i] + bhhb[i];
    }
    for (int i = id; i < 128 * 1024; i += st) {
        int l = i >> 10, k = i & 1023;
        g_fcw[i] = __float2bfloat16(l < LT ? fcw[l * 1024 + k] : 0.f);
    }
}

__global__ void k_gather(const float* emb, const int* x) {
    int id = blockIdx.x * 256 + threadIdx.x;   // 8192*256 = 2,097,152 exactly
    int m = id >> 6, ch = id & 63;
    int t = m >> 6, b = m & 63;
    int tok = x[b * TLEN + t];
    const float4* s = (const float4*)(emb + (size_t)tok * EMBD + ch * 8);
    float4 u = s[0], v = s[1];
    __nv_bfloat162 pk[4];
    pk[0] = __float22bfloat162_rn(make_float2(u.x, u.y));
    pk[1] = __float22bfloat162_rn(make_float2(u.z, u.w));
    pk[2] = __float22bfloat162_rn(make_float2(v.x, v.y));
    pk[3] = __float22bfloat162_rn(make_float2(v.z, v.w));
    *(uint4*)(g_A + (size_t)m * EMBD + ch * 8) = *(const uint4*)pk;
}

// C[m][n] = sum_k A[m][k]*B[n][k], 128x128 tiles, bf16 MMA, fp32 accum.
// mode 0: A=g_A (K=512), B=g_Wih (N=4096) -> g_G (+g_bias)
// mode 1: A=concat(Hf,Hb) (K=1024), B=g_fcw (N=128) -> g_em (+fcb, n<48)
__global__ void __launch_bounds__(256) k_gemm(int mode, const float* fcb) {
    __shared__ __nv_bfloat16 As[2][128 * 40];
    __shared__ __nv_bfloat16 Bs[2][128 * 40];

    int tid = threadIdx.x, lane = tid & 31, warp = tid >> 5;
    int wm = warp >> 2, wn = warp & 3;              // 2 x 4 warp grid, tile 64x32
    int m0 = blockIdx.y * 128, n0 = blockIdx.x * 128;
    int KC = mode ? 32 : 16;

    float acc[4][4][4];
    #pragma unroll
    for (int a = 0; a < 4; a++)
        #pragma unroll
        for (int b = 0; b < 4; b++)
            #pragma unroll
            for (int c = 0; c < 4; c++) acc[a][b][c] = 0.f;

    auto load_stage = [&](int kc, int s) {
        #pragma unroll
        for (int i = 0; i < 2; i++) {
            int c = tid + i * 256;
            int row = c >> 2, seg = c & 3;
            const __nv_bfloat16* sa;
            if (mode == 0)
                sa = g_A + (size_t)(m0 + row) * 512 + kc * 32 + seg * 8;
            else if (kc < 16)
                sa = g_H + (size_t)(m0 + row) * 512 + kc * 32 + seg * 8;
            else
                sa = g_H + (size_t)MR * HD + (size_t)(m0 + row) * 512 + (kc - 16) * 32 + seg * 8;
            cp_async16(&As[s][row * 40 + seg * 8], sa);
            const __nv_bfloat16* sb;
            if (mode == 0)
                sb = g_Wih + (size_t)(n0 + row) * 512 + kc * 32 + seg * 8;
            else
                sb = g_fcw + (size_t)(n0 + row) * 1024 + kc * 32 + seg * 8;
            cp_async16(&Bs[s][row * 40 + seg * 8], sb);
        }
    };

    load_stage(0, 0); cp_commit();
    for (int kc = 0; kc < KC; kc++) {
        int s = kc & 1;
        if (kc + 1 < KC) { load_stage(kc + 1, s ^ 1); cp_commit(); cp_wait1(); }
        else cp_wait0();
        __syncthreads();
        #pragma unroll
        for (int kk = 0; kk < 32; kk += 16) {
            int col = kk + (lane & 3) * 2;
            uint32_t a[4][4], bf[4][2];
            #pragma unroll
            for (int mi = 0; mi < 4; mi++) {
                int row = wm * 64 + mi * 16 + (lane >> 2);
                a[mi][0] = *(const uint32_t*)&As[s][row * 40 + col];
                a[mi][1] = *(const uint32_t*)&As[s][(row + 8) * 40 + col];
                a[mi][2] = *(const uint32_t*)&As[s][row * 40 + col + 8];
                a[mi][3] = *(const uint32_t*)&As[s][(row + 8) * 40 + col + 8];
            }
            #pragma unroll
            for (int ni = 0; ni < 4; ni++) {
                int n = wn * 32 + ni * 8 + (lane >> 2);
                bf[ni][0] = *(const uint32_t*)&Bs[s][n * 40 + col];
                bf[ni][1] = *(const uint32_t*)&Bs[s][n * 40 + col + 8];
            }
            #pragma unroll
            for (int mi = 0; mi < 4; mi++)
                #pragma unroll
                for (int ni = 0; ni < 4; ni++)
                    mma16816(acc[mi][ni], a[mi], bf[ni]);
        }
        __syncthreads();
    }

    #pragma unroll
    for (int mi = 0; mi < 4; mi++) {
        #pragma unroll
        for (int ni = 0; ni < 4; ni++) {
            int m = m0 + wm * 64 + mi * 16 + (lane >> 2);
            int n = n0 + wn * 32 + ni * 8 + (lane & 3) * 2;
            if (mode == 0) {
                int dir = n >> 11, r = n & 2047;
                size_t o1 = ((size_t)dir * MR + m) * NG + r;
                size_t o2 = ((size_t)dir * MR + m + 8) * NG + r;
                g_G[o1]     = acc[mi][ni][0] + g_bias[n];
                g_G[o1 + 1] = acc[mi][ni][1] + g_bias[n + 1];
                g_G[o2]     = acc[mi][ni][2] + g_bias[n];
                g_G[o2 + 1] = acc[mi][ni][3] + g_bias[n + 1];
            } else {
                if (n < LT) {
                    g_em[(size_t)m * LT + n]       = acc[mi][ni][0] + fcb[n];
                    g_em[(size_t)(m + 8) * LT + n] = acc[mi][ni][2] + fcb[n];
                }
                if (n + 1 < LT) {
                    g_em[(size_t)m * LT + n + 1]       = acc[mi][ni][1] + fcb[n + 1];
                    g_em[(size_t)(m + 8) * LT + n + 1] = acc[mi][ni][3] + fcb[n + 1];
                }
            }
        }
    }
}

// Persistent bidirectional LSTM. 128 CTAs: dir = blk>>6, 8 h-channels each.
__global__ void __launch_bounds__(256, 1) k_lstm() {
    extern __shared__ char smem[];
    __nv_bfloat16* whh_s = (__nv_bfloat16*)smem;             // 32 x 520
    __nv_bfloat16* hp_s  = whh_s + 32 * 520;                 // 64 x 520
    float* gates_s = (float*)(hp_s + 64 * 520);              // 64 x 32
    float* c_s     = gates_s + 64 * 32;                      // 64 x 8
    __nv_bfloat16* h_s = (__nv_bfloat16*)(c_s + 64 * 8);     // 64 x 8

    int tid = threadIdx.x, lane = tid & 31, warp = tid >> 5;
    int dir = blockIdx.x >> 6, cta = blockIdx.x & 63, c0 = cta * 8;
    int wm = warp & 3, wn = warp >> 2;                       // 4(M) x 2(N)

    for (int i = tid; i < 32 * 512; i += 256) {
        int j = i >> 9, k = i & 511;
        int r = ((j >> 3) << 9) + c0 + (j & 7);              // gate*512 + channel
        whh_s[j * 520 + k] = g_Whh[((size_t)dir * NG + r) * HD + k];
    }
    for (int i = tid; i < 64 * 8; i += 256) c_s[i] = 0.f;
    __syncthreads();

    for (int s = 0; s < TLEN; s++) {
        int t = dir ? (TLEN - 1 - s) : s;
        if (s > 0) {
            if (tid == 0) {
                while (atomicAdd(&g_cnt[dir], 0) < s * 64) { }
                __threadfence();
            }
            __syncthreads();
            int pt = dir ? t + 1 : t - 1;
            for (int i = tid; i < 4096; i += 256) {
                int b = i >> 6, seg = i & 63;
                cp_async16(&hp_s[b * 520 + seg * 8],
                           g_H + ((size_t)dir * MR + (size_t)pt * 64 + b) * HD + seg * 8);
            }
            cp_commit();
        }
        // input gates (bias already folded)
        const float* Gp = g_G + ((size_t)dir * MR + (size_t)t * 64) * NG;
        for (int i = tid; i < 2048; i += 256) {
            int b = i >> 5, j = i & 31;
            int r = ((j >> 3) << 9) + c0 + (j & 7);
            gates_s[b * 32 + j] = Gp[(size_t)b * NG + r];
        }
        if (s > 0) {
            cp_wait0();
            __syncthreads();
            float c[2][4] = {{0, 0, 0, 0}, {0, 0, 0, 0}};
            #pragma unroll 4
            for (int kk = 0; kk < 512; kk += 16) {
                int col = kk + (lane & 3) * 2;
                int row = wm * 16 + (lane >> 2);
                uint32_t a[4];
                a[0] = *(const uint32_t*)&hp_s[row * 520 + col];
                a[1] = *(const uint32_t*)&hp_s[(row + 8) * 520 + col];
                a[2] = *(const uint32_t*)&hp_s[row * 520 + col + 8];
                a[3] = *(const uint32_t*)&hp_s[(row + 8) * 520 + col + 8];
                #pragma unroll
                for (int f = 0; f < 2; f++) {
                    int n = wn * 16 + f * 8 + (lane >> 2);
                    uint32_t bb[2];
                    bb[0] = *(const uint32_t*)&whh_s[n * 520 + col];
                    bb[1] = *(const uint32_t*)&whh_s[n * 520 + col + 8];
                    mma16816(c[f], a, bb);
                }
            }
            #pragma unroll
            for (int f = 0; f < 2; f++) {
                int r0 = wm * 16 + (lane >> 2);
                int n  = wn * 16 + f * 8 + (lane & 3) * 2;
                gates_s[r0 * 32 + n]           += c[f][0];
                gates_s[r0 * 32 + n + 1]       += c[f][1];
                gates_s[(r0 + 8) * 32 + n]     += c[f][2];
                gates_s[(r0 + 8) * 32 + n + 1] += c[f][3];
            }
        }
        __syncthreads();
        #pragma unroll
        for (int it = 0; it < 2; it++) {
            int item = tid + it * 256;
            int b = item >> 3, ch = item & 7;
            float gi = gates_s[b * 32 + ch];
            float gf = gates_s[b * 32 + ch + 8];
            float gg = gates_s[b * 32 + ch + 16];
            float go = gates_s[b * 32 + ch + 24];
            float cc = sig_f(gf) * c_s[b * 8 + ch] + sig_f(gi) * tanh_f(gg);
            c_s[b * 8 + ch] = cc;
            h_s[b * 8 + ch] = __float2bfloat16(sig_f(go) * tanh_f(cc));
        }
        __syncthreads();
        if (tid < 64) {
            *(uint4*)(g_H + ((size_t)dir * MR + (size_t)t * 64 + tid) * HD + c0) =
                *(const uint4*)&h_s[tid * 8];
        }
        __syncthreads();
        if (tid == 0) { __threadfence(); atomicAdd(&g_cnt[dir], 1); }
    }
}

__global__ void k_crf(const float* strans, const float* etrans, const float* trans,
                      const int* tags) {
    __shared__ float trT[48 * 49];
    __shared__ float alpha[48];
    __shared__ float red[64];
    int b = blockIdx.x, tid = threadIdx.x;
    for (int idx = tid; idx < 2304; idx += 64) {
        int i = idx / 48, j = idx % 48;
        trT[j * 49 + i] = trans[idx];
    }
    float num = 0.f;
    for (int t = tid; t < TLEN; t += 64) {
        int tg = tags[b * TLEN + t];
        num += g_em[((size_t)t * 64 + b) * LT + tg];
        if (t > 0) num += trans[tags[b * TLEN + t - 1] * 48 + tg];
        else       num += strans[tg];
        if (t == TLEN - 1) num += etrans[tg];
    }
    red[tid] = num; __syncthreads();
    for (int o = 32; o > 0; o >>= 1) { if (tid < o) red[tid] += red[tid + o]; __syncthreads(); }
    num = red[0];
    __syncthreads();
    if (tid < 48) alpha[tid] = strans[tid] + g_em[(size_t)b * LT + tid];
    __syncthreads();
    for (int t = 1; t < TLEN; t++) {
        float nv = 0.f;
        if (tid < 48) {
            float e = g_em[((size_t)t * 64 + b) * LT + tid];
            float mx = -1e30f;
            #pragma unroll 8
            for (int i = 0; i < 48; i++) mx = fmaxf(mx, alpha[i] + trT[tid * 49 + i]);
            float sum = 0.f;
            #pragma unroll 8
            for (int i = 0; i < 48; i++) sum += __expf(alpha[i] + trT[tid * 49 + i] - mx);
            nv = mx + __logf(sum) + e;
        }
        __syncthreads();
        if (tid < 48) alpha[tid] = nv;
        __syncthreads();
    }
    float v = (tid < 48) ? alpha[tid] + etrans[tid] : -1e30f;
    red[tid] = v; __syncthreads();
    for (int o = 32; o > 0; o >>= 1) { if (tid < o) red[tid] = fmaxf(red[tid], red[tid + o]); __syncthreads(); }
    float mx = red[0]; __syncthreads();
    red[tid] = (tid < 48) ? __expf(v - mx) : 0.f; __syncthreads();
    for (int o = 32; o > 0; o >>= 1) { if (tid < o) red[tid] += red[tid + o]; __syncthreads(); }
    if (tid == 0) g_llh[b] = num - (mx + __logf(red[0]));
}

__global__ void k_fin(float* out) {
    __shared__ float red[64];
    red[threadIdx.x] = g_llh[threadIdx.x]; __syncthreads();
    for (int o = 32; o > 0; o >>= 1) { if (threadIdx.x < o) red[threadIdx.x] += red[threadIdx.x + o]; __syncthreads(); }
    if (threadIdx.x == 0) out[0] = -red[0] / 64.f;
}

// ---------------- launch -----------------------------------------------------
extern "C" void kernel_launch(void* const* d_in, const int* in_sizes, int n_in,
                              void* d_out, int out_size) {
    const float* emb    = (const float*)d_in[0];
    const float* wihf   = (const float*)d_in[1];
    const float* whhf   = (const float*)d_in[2];
    const float* bihf   = (const float*)d_in[3];
    const float* bhhf   = (const float*)d_in[4];
    const float* wihb   = (const float*)d_in[5];
    const float* whhb   = (const float*)d_in[6];
    const float* bihb   = (const float*)d_in[7];
    const float* bhhb   = (const float*)d_in[8];
    const float* fcw    = (const float*)d_in[9];
    const float* fcb    = (const float*)d_in[10];
    const float* strans = (const float*)d_in[11];
    const float* etrans = (const float*)d_in[12];
    const float* trans  = (const float*)d_in[13];
    const int*   x      = (const int*)d_in[14];
    const int*   tags   = (const int*)d_in[15];
    float* out = (float*)d_out;

    cudaFuncSetAttribute(k_lstm, cudaFuncAttributeMaxDynamicSharedMemorySize, 113 * 1024);

    k_reset<<<1, 32>>>();
    k_prep<<<2048, 256>>>(wihf, whhf, bihf, bhhf, wihb, whhb, bihb, bhhb, fcw);
    k_gather<<<8192, 256>>>(emb, x);
    k_gemm<<<dim3(32, 256), 256>>>(0, fcb);
    k_lstm<<<128, 256, 111104>>>();
    k_gemm<<<dim3(1, 256), 256>>>(1, fcb);
    k_crf<<<64, 64>>>(strans, etrans, trans, tags);
    k_fin<<<1, 64>>>(out);
}

// round 4
// speedup vs baseline: 1.3185x; 1.3185x over previous
#include <cuda_runtime.h>
#include <cuda_bf16.h>
#include <stdint.h>

#define TLEN  512
#define BATCH 64
#define EMBD  512
#define HD    512
#define NG    2048
#define LT    48
#define MR    (TLEN*BATCH)   // 32768

// ---------------- device scratch (static globals, no allocation) ------------
__device__ __nv_bfloat16 g_A  [(size_t)MR*EMBD];     // gathered embeddings, m = t*64+b
__device__ __nv_bfloat16 g_Wih[(size_t)2*NG*EMBD];   // [dir*2048+r][k]
__device__ __nv_bfloat16 g_Whh[(size_t)2*NG*HD];
__device__ float         g_bias[2*NG];
__device__ __nv_bfloat16 g_fcw[(size_t)128*1024];    // fc_w padded to 128 rows
__device__ __nv_bfloat16 g_G  [(size_t)2*MR*NG];     // input gates + bias (bf16)
__device__ __nv_bfloat16 g_H  [(size_t)2*MR*HD];     // hidden states
__device__ float         g_em [(size_t)MR*LT];       // emissions
__device__ float         g_llh[BATCH];
__device__ int           g_cnt[2];

// ---------------- helpers ----------------------------------------------------
__device__ __forceinline__ void cp_async16(void* smem, const void* gmem) {
    uint32_t s = (uint32_t)__cvta_generic_to_shared(smem);
    asm volatile("cp.async.cg.shared.global [%0], [%1], 16;\n" :: "r"(s), "l"(gmem));
}
__device__ __forceinline__ void cp_commit() { asm volatile("cp.async.commit_group;\n"); }
__device__ __forceinline__ void cp_wait0()  { asm volatile("cp.async.wait_group 0;\n"); }
__device__ __forceinline__ void cp_wait1()  { asm volatile("cp.async.wait_group 1;\n"); }

__device__ __forceinline__ void mma16816(float* c, const uint32_t* a, const uint32_t* b) {
    asm volatile("mma.sync.aligned.m16n8k16.row.col.f32.bf16.bf16.f32 "
                 "{%0,%1,%2,%3},{%4,%5,%6,%7},{%8,%9},{%0,%1,%2,%3};\n"
                 : "+f"(c[0]), "+f"(c[1]), "+f"(c[2]), "+f"(c[3])
                 : "r"(a[0]), "r"(a[1]), "r"(a[2]), "r"(a[3]), "r"(b[0]), "r"(b[1]));
}
__device__ __forceinline__ float tanh_f(float x) {
    float y; asm("tanh.approx.f32 %0, %1;" : "=f"(y) : "f"(x)); return y;
}
__device__ __forceinline__ float sig_f(float x) { return 1.f / (1.f + __expf(-x)); }

__device__ __forceinline__ int ld_acq(const int* p) {
    int v; asm volatile("ld.acquire.gpu.global.b32 %0, [%1];" : "=r"(v) : "l"(p)); return v;
}
__device__ __forceinline__ void red_add(int* p, int v) {
    asm volatile("red.global.add.s32 [%0], %1;" :: "l"(p), "r"(v));
}

// ---------------- kernels ----------------------------------------------------
__global__ void k_reset() { if (threadIdx.x < 2) g_cnt[threadIdx.x] = 0; }

__global__ void k_prep(const float* wihf, const float* whhf, const float* bihf,
                       const float* bhhf, const float* wihb, const float* whhb,
                       const float* bihb, const float* bhhb, const float* fcw) {
    int id = blockIdx.x * blockDim.x + threadIdx.x;
    int st = gridDim.x * blockDim.x;
    const int NW = NG * EMBD;
    for (int i = id; i < NW; i += st) {
        g_Wih[i]      = __float2bfloat16(wihf[i]);
        g_Wih[NW + i] = __float2bfloat16(wihb[i]);
        g_Whh[i]      = __float2bfloat16(whhf[i]);
        g_Whh[NW + i] = __float2bfloat16(whhb[i]);
    }
    for (int i = id; i < NG; i += st) {
        g_bias[i]      = bihf[i] + bhhf[i];
        g_bias[NG + i] = bihb[i] + bhhb[i];
    }
    for (int i = id; i < 128 * 1024; i += st) {
        int l = i >> 10, k = i & 1023;
        g_fcw[i] = __float2bfloat16(l < LT ? fcw[l * 1024 + k] : 0.f);
    }
}

__global__ void k_gather(const float* emb, const int* x) {
    int id = blockIdx.x * 256 + threadIdx.x;   // 8192*256 = 2,097,152 exactly
    int m = id >> 6, ch = id & 63;
    int t = m >> 6, b = m & 63;
    int tok = x[b * TLEN + t];
    const float4* s = (const float4*)(emb + (size_t)tok * EMBD + ch * 8);
    float4 u = s[0], v = s[1];
    __nv_bfloat162 pk[4];
    pk[0] = __float22bfloat162_rn(make_float2(u.x, u.y));
    pk[1] = __float22bfloat162_rn(make_float2(u.z, u.w));
    pk[2] = __float22bfloat162_rn(make_float2(v.x, v.y));
    pk[3] = __float22bfloat162_rn(make_float2(v.z, v.w));
    *(uint4*)(g_A + (size_t)m * EMBD + ch * 8) = *(const uint4*)pk;
}

// C[m][n] = sum_k A[m][k]*B[n][k], 128x128 tiles, bf16 MMA, fp32 accum.
// mode 0: A=g_A (K=512), B=g_Wih (N=4096) -> g_G bf16 (+g_bias)
// mode 1: A=concat(Hf,Hb) (K=1024), B=g_fcw (N=128) -> g_em fp32 (+fcb, n<48)
__global__ void __launch_bounds__(256, 2) k_gemm(int mode, const float* fcb) {
    __shared__ __nv_bfloat16 As[2][128 * 40];
    __shared__ __nv_bfloat16 Bs[2][128 * 40];

    int tid = threadIdx.x, lane = tid & 31, warp = tid >> 5;
    int wm = warp >> 2, wn = warp & 3;              // 2 x 4 warp grid, tile 64x32
    int m0 = blockIdx.y * 128, n0 = blockIdx.x * 128;
    int KC = mode ? 32 : 16;

    float acc[4][4][4];
    #pragma unroll
    for (int a = 0; a < 4; a++)
        #pragma unroll
        for (int b = 0; b < 4; b++)
            #pragma unroll
            for (int c = 0; c < 4; c++) acc[a][b][c] = 0.f;

    auto load_stage = [&](int kc, int s) {
        #pragma unroll
        for (int i = 0; i < 2; i++) {
            int c = tid + i * 256;
            int row = c >> 2, seg = c & 3;
            const __nv_bfloat16* sa;
            if (mode == 0)
                sa = g_A + (size_t)(m0 + row) * 512 + kc * 32 + seg * 8;
            else if (kc < 16)
                sa = g_H + (size_t)(m0 + row) * 512 + kc * 32 + seg * 8;
            else
                sa = g_H + (size_t)MR * HD + (size_t)(m0 + row) * 512 + (kc - 16) * 32 + seg * 8;
            cp_async16(&As[s][row * 40 + seg * 8], sa);
            const __nv_bfloat16* sb;
            if (mode == 0)
                sb = g_Wih + (size_t)(n0 + row) * 512 + kc * 32 + seg * 8;
            else
                sb = g_fcw + (size_t)(n0 + row) * 1024 + kc * 32 + seg * 8;
            cp_async16(&Bs[s][row * 40 + seg * 8], sb);
        }
    };

    load_stage(0, 0); cp_commit();
    for (int kc = 0; kc < KC; kc++) {
        int s = kc & 1;
        if (kc + 1 < KC) { load_stage(kc + 1, s ^ 1); cp_commit(); cp_wait1(); }
        else cp_wait0();
        __syncthreads();
        #pragma unroll
        for (int kk = 0; kk < 32; kk += 16) {
            int col = kk + (lane & 3) * 2;
            uint32_t a[4][4], bf[4][2];
            #pragma unroll
            for (int mi = 0; mi < 4; mi++) {
                int row = wm * 64 + mi * 16 + (lane >> 2);
                a[mi][0] = *(const uint32_t*)&As[s][row * 40 + col];
                a[mi][1] = *(const uint32_t*)&As[s][(row + 8) * 40 + col];
                a[mi][2] = *(const uint32_t*)&As[s][row * 40 + col + 8];
                a[mi][3] = *(const uint32_t*)&As[s][(row + 8) * 40 + col + 8];
            }
            #pragma unroll
            for (int ni = 0; ni < 4; ni++) {
                int n = wn * 32 + ni * 8 + (lane >> 2);
                bf[ni][0] = *(const uint32_t*)&Bs[s][n * 40 + col];
                bf[ni][1] = *(const uint32_t*)&Bs[s][n * 40 + col + 8];
            }
            #pragma unroll
            for (int mi = 0; mi < 4; mi++)
                #pragma unroll
                for (int ni = 0; ni < 4; ni++)
                    mma16816(acc[mi][ni], a[mi], bf[ni]);
        }
        __syncthreads();
    }

    #pragma unroll
    for (int mi = 0; mi < 4; mi++) {
        #pragma unroll
        for (int ni = 0; ni < 4; ni++) {
            int m = m0 + wm * 64 + mi * 16 + (lane >> 2);
            int n = n0 + wn * 32 + ni * 8 + (lane & 3) * 2;
            if (mode == 0) {
                int dir = n >> 11, r = n & 2047;
                size_t o1 = ((size_t)dir * MR + m) * NG + r;
                size_t o2 = ((size_t)dir * MR + m + 8) * NG + r;
                float b0 = g_bias[n], b1 = g_bias[n + 1];
                __nv_bfloat162 v1 = __float22bfloat162_rn(
                    make_float2(acc[mi][ni][0] + b0, acc[mi][ni][1] + b1));
                __nv_bfloat162 v2 = __float22bfloat162_rn(
                    make_float2(acc[mi][ni][2] + b0, acc[mi][ni][3] + b1));
                *(__nv_bfloat162*)&g_G[o1] = v1;
                *(__nv_bfloat162*)&g_G[o2] = v2;
            } else {
                if (n < LT) {
                    g_em[(size_t)m * LT + n]       = acc[mi][ni][0] + fcb[n];
                    g_em[(size_t)(m + 8) * LT + n] = acc[mi][ni][2] + fcb[n];
                }
                if (n + 1 < LT) {
                    g_em[(size_t)m * LT + n + 1]       = acc[mi][ni][1] + fcb[n + 1];
                    g_em[(size_t)(m + 8) * LT + n + 1] = acc[mi][ni][3] + fcb[n + 1];
                }
            }
        }
    }
}

// Persistent bidirectional LSTM. 128 CTAs: dir = blk>>6, 8 h-channels each.
// G prefetched one step ahead (off critical path); c state in registers;
// acquire-load poll / red.add arrive.
__global__ void __launch_bounds__(256, 1) k_lstm() {
    extern __shared__ char smem[];
    __nv_bfloat16* whh_s = (__nv_bfloat16*)smem;               // 32 x 520
    __nv_bfloat16* hp_s  = whh_s + 32 * 520;                   // 64 x 520
    float* gates_s = (float*)(hp_s + 64 * 520);                // 64 x 32
    __nv_bfloat16* gbuf = (__nv_bfloat16*)(gates_s + 64 * 32); // 2 x (64 x 32)

    int tid = threadIdx.x, lane = tid & 31, warp = tid >> 5;
    int dir = blockIdx.x >> 6, cta = blockIdx.x & 63, c0 = cta * 8;
    int wm = warp & 3, wn = warp >> 2;                         // 4(M) x 2(N)

    for (int i = tid; i < 32 * 512; i += 256) {
        int j = i >> 9, k = i & 511;
        int r = ((j >> 3) << 9) + c0 + (j & 7);                // gate*512 + channel
        whh_s[j * 520 + k] = g_Whh[((size_t)dir * NG + r) * HD + k];
    }
    float2 creg = make_float2(0.f, 0.f);
    int pb = tid >> 2, pc = (tid & 3) * 2;                     // pointwise ownership
    int gb = tid >> 2, gg = tid & 3;                           // G-prefetch ownership

    auto prefG = [&](int t, int buf) {
        const __nv_bfloat16* src =
            g_G + ((size_t)dir * MR + (size_t)t * 64 + gb) * NG + gg * 512 + c0;
        cp_async16(&gbuf[buf * 2048 + gb * 32 + gg * 8], src);
    };
    prefG(dir ? 511 : 0, 0);
    cp_commit();

    for (int s = 0; s < TLEN; s++) {
        int t = dir ? (TLEN - 1 - s) : s;
        if (s > 0) {
            if (tid == 0) { while (ld_acq(&g_cnt[dir]) < s * 64) { } }
            __syncthreads();
            int pt = dir ? t + 1 : t - 1;
            for (int i = tid; i < 4096; i += 256) {
                int b = i >> 6, seg = i & 63;
                cp_async16(&hp_s[b * 520 + seg * 8],
                           g_H + ((size_t)dir * MR + (size_t)pt * 64 + b) * HD + seg * 8);
            }
            cp_commit();
        }
        if (s + 1 < TLEN) prefG(dir ? TLEN - 2 - s : s + 1, (s + 1) & 1);
        cp_commit();
        cp_wait1();                 // current h + current G done; next G may fly
        __syncthreads();

        if (s > 0) {
            float c[2][4] = {{0, 0, 0, 0}, {0, 0, 0, 0}};
            #pragma unroll 4
            for (int kk = 0; kk < 512; kk += 16) {
                int col = kk + (lane & 3) * 2;
                int row = wm * 16 + (lane >> 2);
                uint32_t a[4];
                a[0] = *(const uint32_t*)&hp_s[row * 520 + col];
                a[1] = *(const uint32_t*)&hp_s[(row + 8) * 520 + col];
                a[2] = *(const uint32_t*)&hp_s[row * 520 + col + 8];
                a[3] = *(const uint32_t*)&hp_s[(row + 8) * 520 + col + 8];
                #pragma unroll
                for (int f = 0; f < 2; f++) {
                    int n = wn * 16 + f * 8 + (lane >> 2);
                    uint32_t bb[2];
                    bb[0] = *(const uint32_t*)&whh_s[n * 520 + col];
                    bb[1] = *(const uint32_t*)&whh_s[n * 520 + col + 8];
                    mma16816(c[f], a, bb);
                }
            }
            const __nv_bfloat16* gB = &gbuf[(s & 1) * 2048];
            #pragma unroll
            for (int f = 0; f < 2; f++) {
                int r0 = wm * 16 + (lane >> 2);
                int n  = wn * 16 + f * 8 + (lane & 3) * 2;
                __nv_bfloat162 g0 = *(const __nv_bfloat162*)&gB[r0 * 32 + n];
                __nv_bfloat162 g1 = *(const __nv_bfloat162*)&gB[(r0 + 8) * 32 + n];
                gates_s[r0 * 32 + n]           = c[f][0] + __bfloat162float(g0.x);
                gates_s[r0 * 32 + n + 1]       = c[f][1] + __bfloat162float(g0.y);
                gates_s[(r0 + 8) * 32 + n]     = c[f][2] + __bfloat162float(g1.x);
                gates_s[(r0 + 8) * 32 + n + 1] = c[f][3] + __bfloat162float(g1.y);
            }
        } else {
            for (int i = tid; i < 2048; i += 256)
                gates_s[i] = __bfloat162float(gbuf[i]);
        }
        __syncthreads();
        {
            float gi0 = gates_s[pb * 32 + pc],      gi1 = gates_s[pb * 32 + pc + 1];
            float gf0 = gates_s[pb * 32 + pc + 8],  gf1 = gates_s[pb * 32 + pc + 9];
            float gg0 = gates_s[pb * 32 + pc + 16], gg1 = gates_s[pb * 32 + pc + 17];
            float go0 = gates_s[pb * 32 + pc + 24], go1 = gates_s[pb * 32 + pc + 25];
            creg.x = sig_f(gf0) * creg.x + sig_f(gi0) * tanh_f(gg0);
            creg.y = sig_f(gf1) * creg.y + sig_f(gi1) * tanh_f(gg1);
            float h0 = sig_f(go0) * tanh_f(creg.x);
            float h1 = sig_f(go1) * tanh_f(creg.y);
            __nv_bfloat162 hv = __float22bfloat162_rn(make_float2(h0, h1));
            *(__nv_bfloat162*)(g_H + ((size_t)dir * MR + (size_t)t * 64 + pb) * HD + c0 + pc) = hv;
        }
        __syncthreads();
        if (tid == 0) { __threadfence(); red_add(&g_cnt[dir], 1); }
    }
}

// CRF forward: exp-trick logsumexp, 256 threads per sequence.
__global__ void __launch_bounds__(256) k_crf(const float* strans, const float* etrans,
                                             const float* trans, const int* tags) {
    __shared__ float Et[48 * 49];
    __shared__ float alpha[48];
    __shared__ float p[48];
    __shared__ float part[4 * 48];
    __shared__ float red[256];
    __shared__ float sm_m;
    int b = blockIdx.x, tid = threadIdx.x;
    for (int i = tid; i < 2304; i += 256) {
        int r = i / 48, c = i - r * 48;
        Et[c * 49 + r] = __expf(trans[i]);
    }
    float num = 0.f;
    for (int t = tid; t < TLEN; t += 256) {
        int tg = tags[b * TLEN + t];
        num += g_em[((size_t)t * 64 + b) * LT + tg];
        num += (t > 0) ? trans[tags[b * TLEN + t - 1] * 48 + tg] : strans[tg];
        if (t == TLEN - 1) num += etrans[tg];
    }
    red[tid] = num; __syncthreads();
    for (int o = 128; o > 0; o >>= 1) { if (tid < o) red[tid] += red[tid + o]; __syncthreads(); }
    num = red[0];
    if (tid < 48) alpha[tid] = strans[tid] + g_em[(size_t)b * LT + tid];
    __syncthreads();
    for (int t = 1; t < TLEN; t++) {
        if (tid < 32) {
            float v = alpha[tid];
            if (tid < 16) v = fmaxf(v, alpha[tid + 32]);
            #pragma unroll
            for (int o = 16; o > 0; o >>= 1) v = fmaxf(v, __shfl_xor_sync(0xffffffffu, v, o));
            if (tid == 0) sm_m = v;
        }
        __syncthreads();
        if (tid < 48) p[tid] = __expf(alpha[tid] - sm_m);
        __syncthreads();
        int q = tid >> 6, j = tid & 63;
        if (j < 48) {
            float s = 0.f;
            #pragma unroll
            for (int u = 0; u < 12; u++) { int i = q * 12 + u; s += p[i] * Et[j * 49 + i]; }
            part[q * 48 + j] = s;
        }
        __syncthreads();
        if (tid < 48) {
            float s = part[tid] + part[48 + tid] + part[96 + tid] + part[144 + tid];
            alpha[tid] = g_em[((size_t)t * 64 + b) * LT + tid] + sm_m + __logf(s);
        }
        __syncthreads();
    }
    float v = (tid < 48) ? alpha[tid] + etrans[tid] : -1e30f;
    red[tid] = v; __syncthreads();
    for (int o = 128; o > 0; o >>= 1) { if (tid < o) red[tid] = fmaxf(red[tid], red[tid + o]); __syncthreads(); }
    float mx = red[0]; __syncthreads();
    red[tid] = (tid < 48) ? __expf(v - mx) : 0.f; __syncthreads();
    for (int o = 128; o > 0; o >>= 1) { if (tid < o) red[tid] += red[tid + o]; __syncthreads(); }
    if (tid == 0) g_llh[b] = num - (mx + __logf(red[0]));
}

__global__ void k_fin(float* out) {
    __shared__ float red[64];
    red[threadIdx.x] = g_llh[threadIdx.x]; __syncthreads();
    for (int o = 32; o > 0; o >>= 1) {
        if (threadIdx.x < o) red[threadIdx.x] += red[threadIdx.x + o];
        __syncthreads();
    }
    if (threadIdx.x == 0) out[0] = -red[0] / 64.f;
}

// ---------------- launch -----------------------------------------------------
extern "C" void kernel_launch(void* const* d_in, const int* in_sizes, int n_in,
                              void* d_out, int out_size) {
    const float* emb    = (const float*)d_in[0];
    const float* wihf   = (const float*)d_in[1];
    const float* whhf   = (const float*)d_in[2];
    const float* bihf   = (const float*)d_in[3];
    const float* bhhf   = (const float*)d_in[4];
    const float* wihb   = (const float*)d_in[5];
    const float* whhb   = (const float*)d_in[6];
    const float* bihb   = (const float*)d_in[7];
    const float* bhhb   = (const float*)d_in[8];
    const float* fcw    = (const float*)d_in[9];
    const float* fcb    = (const float*)d_in[10];
    const float* strans = (const float*)d_in[11];
    const float* etrans = (const float*)d_in[12];
    const float* trans  = (const float*)d_in[13];
    const int*   x      = (const int*)d_in[14];
    const int*   tags   = (const int*)d_in[15];
    float* out = (float*)d_out;

    const int lstm_smem = 32 * 520 * 2 + 64 * 520 * 2 + 64 * 32 * 4 + 2 * 64 * 32 * 2;
    cudaFuncSetAttribute(k_lstm, cudaFuncAttributeMaxDynamicSharedMemorySize, lstm_smem);

    k_reset<<<1, 32>>>();
    k_prep<<<2048, 256>>>(wihf, whhf, bihf, bhhf, wihb, whhb, bihb, bhhb, fcw);
    k_gather<<<8192, 256>>>(emb, x);
    k_gemm<<<dim3(32, 256), 256>>>(0, fcb);
    k_lstm<<<128, 256, lstm_smem>>>();
    k_gemm<<<dim3(1, 256), 256>>>(1, fcb);
    k_crf<<<64, 256>>>(strans, etrans, trans, tags);
    k_fin<<<1, 64>>>(out);
}

// round 5
// speedup vs baseline: 1.3282x; 1.0074x over previous
#include <cuda_runtime.h>
#include <cuda_bf16.h>
#include <stdint.h>

#define TLEN  512
#define BATCH 64
#define EMBD  512
#define HD    512
#define NG    2048
#define LT    48
#define MR    (TLEN*BATCH)   // 32768

// ---------------- device scratch (static globals, no allocation) ------------
__device__ __nv_bfloat16 g_A  [(size_t)MR*EMBD];     // gathered embeddings, m = t*64+b
__device__ __nv_bfloat16 g_Wih[(size_t)2*NG*EMBD];   // [dir*2048+r][k]
__device__ __nv_bfloat16 g_Whh[(size_t)2*NG*HD];
__device__ float         g_bias[2*NG];
__device__ __nv_bfloat16 g_fcw[(size_t)128*1024];    // fc_w padded to 128 rows
__device__ __nv_bfloat16 g_H  [(size_t)2*MR*HD];     // hidden states
__device__ float         g_em [(size_t)MR*LT];       // emissions
__device__ float         g_llh[BATCH];
__device__ int           g_cnt[2];

// ---------------- helpers ----------------------------------------------------
__device__ __forceinline__ void cp_async16(void* smem, const void* gmem) {
    uint32_t s = (uint32_t)__cvta_generic_to_shared(smem);
    asm volatile("cp.async.cg.shared.global [%0], [%1], 16;\n" :: "r"(s), "l"(gmem));
}
__device__ __forceinline__ void cp_commit() { asm volatile("cp.async.commit_group;\n"); }
__device__ __forceinline__ void cp_wait0()  { asm volatile("cp.async.wait_group 0;\n"); }
__device__ __forceinline__ void cp_wait1()  { asm volatile("cp.async.wait_group 1;\n"); }

__device__ __forceinline__ void mma16816(float* c, const uint32_t* a, const uint32_t* b) {
    asm volatile("mma.sync.aligned.m16n8k16.row.col.f32.bf16.bf16.f32 "
                 "{%0,%1,%2,%3},{%4,%5,%6,%7},{%8,%9},{%0,%1,%2,%3};\n"
                 : "+f"(c[0]), "+f"(c[1]), "+f"(c[2]), "+f"(c[3])
                 : "r"(a[0]), "r"(a[1]), "r"(a[2]), "r"(a[3]), "r"(b[0]), "r"(b[1]));
}
__device__ __forceinline__ float tanh_f(float x) {
    float y; asm("tanh.approx.f32 %0, %1;" : "=f"(y) : "f"(x)); return y;
}
__device__ __forceinline__ float sig_f(float x) { return 1.f / (1.f + __expf(-x)); }

__device__ __forceinline__ int ld_acq(const int* p) {
    int v; asm volatile("ld.acquire.gpu.global.b32 %0, [%1];" : "=r"(v) : "l"(p)); return v;
}
__device__ __forceinline__ void red_add(int* p, int v) {
    asm volatile("red.global.add.s32 [%0], %1;" :: "l"(p), "r"(v));
}

// 64x32x512 bf16 MMA: M (64x520 smem) @ W^T (32x520 smem) -> c frags
__device__ __forceinline__ void mat64x32(const __nv_bfloat16* M, const __nv_bfloat16* W,
                                         float (&c)[2][4], int lane, int wm, int wn) {
    #pragma unroll 4
    for (int kk = 0; kk < 512; kk += 16) {
        int col = kk + (lane & 3) * 2;
        int row = wm * 16 + (lane >> 2);
        uint32_t a[4];
        a[0] = *(const uint32_t*)&M[row * 520 + col];
        a[1] = *(const uint32_t*)&M[(row + 8) * 520 + col];
        a[2] = *(const uint32_t*)&M[row * 520 + col + 8];
        a[3] = *(const uint32_t*)&M[(row + 8) * 520 + col + 8];
        #pragma unroll
        for (int f = 0; f < 2; f++) {
            int n = wn * 16 + f * 8 + (lane >> 2);
            uint32_t bb[2];
            bb[0] = *(const uint32_t*)&W[n * 520 + col];
            bb[1] = *(const uint32_t*)&W[n * 520 + col + 8];
            mma16816(c[f], a, bb);
        }
    }
}

// ---------------- kernels ----------------------------------------------------
__global__ void k_reset() { if (threadIdx.x < 2) g_cnt[threadIdx.x] = 0; }

__global__ void k_prep(const float* wihf, const float* whhf, const float* bihf,
                       const float* bhhf, const float* wihb, const float* whhb,
                       const float* bihb, const float* bhhb, const float* fcw) {
    int id = blockIdx.x * blockDim.x + threadIdx.x;
    int st = gridDim.x * blockDim.x;
    const int NW = NG * EMBD;
    for (int i = id; i < NW; i += st) {
        g_Wih[i]      = __float2bfloat16(wihf[i]);
        g_Wih[NW + i] = __float2bfloat16(wihb[i]);
        g_Whh[i]      = __float2bfloat16(whhf[i]);
        g_Whh[NW + i] = __float2bfloat16(whhb[i]);
    }
    for (int i = id; i < NG; i += st) {
        g_bias[i]      = bihf[i] + bhhf[i];
        g_bias[NG + i] = bihb[i] + bhhb[i];
    }
    for (int i = id; i < 128 * 1024; i += st) {
        int l = i >> 10, k = i & 1023;
        g_fcw[i] = __float2bfloat16(l < LT ? fcw[l * 1024 + k] : 0.f);
    }
}

__global__ void k_gather(const float* emb, const int* x) {
    int id = blockIdx.x * 256 + threadIdx.x;   // 8192*256 = 2,097,152 exactly
    int m = id >> 6, ch = id & 63;
    int t = m >> 6, b = m & 63;
    int tok = x[b * TLEN + t];
    const float4* s = (const float4*)(emb + (size_t)tok * EMBD + ch * 8);
    float4 u = s[0], v = s[1];
    __nv_bfloat162 pk[4];
    pk[0] = __float22bfloat162_rn(make_float2(u.x, u.y));
    pk[1] = __float22bfloat162_rn(make_float2(u.z, u.w));
    pk[2] = __float22bfloat162_rn(make_float2(v.x, v.y));
    pk[3] = __float22bfloat162_rn(make_float2(v.z, v.w));
    *(uint4*)(g_A + (size_t)m * EMBD + ch * 8) = *(const uint4*)pk;
}

// Emissions GEMM: em[m][n] = sum_k H[m][k]*fcw[n][k] + fcb[n], K=1024 (concat dirs)
__global__ void __launch_bounds__(256, 2) k_gemm(const float* fcb) {
    __shared__ __nv_bfloat16 As[2][128 * 40];
    __shared__ __nv_bfloat16 Bs[2][128 * 40];

    int tid = threadIdx.x, lane = tid & 31, warp = tid >> 5;
    int wm = warp >> 2, wn = warp & 3;              // 2 x 4 warp grid, tile 64x32
    int m0 = blockIdx.y * 128, n0 = blockIdx.x * 128;
    const int KC = 32;

    float acc[4][4][4];
    #pragma unroll
    for (int a = 0; a < 4; a++)
        #pragma unroll
        for (int b = 0; b < 4; b++)
            #pragma unroll
            for (int c = 0; c < 4; c++) acc[a][b][c] = 0.f;

    auto load_stage = [&](int kc, int s) {
        #pragma unroll
        for (int i = 0; i < 2; i++) {
            int c = tid + i * 256;
            int row = c >> 2, seg = c & 3;
            const __nv_bfloat16* sa;
            if (kc < 16)
                sa = g_H + (size_t)(m0 + row) * 512 + kc * 32 + seg * 8;
            else
                sa = g_H + (size_t)MR * HD + (size_t)(m0 + row) * 512 + (kc - 16) * 32 + seg * 8;
            cp_async16(&As[s][row * 40 + seg * 8], sa);
            const __nv_bfloat16* sb = g_fcw + (size_t)(n0 + row) * 1024 + kc * 32 + seg * 8;
            cp_async16(&Bs[s][row * 40 + seg * 8], sb);
        }
    };

    load_stage(0, 0); cp_commit();
    for (int kc = 0; kc < KC; kc++) {
        int s = kc & 1;
        if (kc + 1 < KC) { load_stage(kc + 1, s ^ 1); cp_commit(); cp_wait1(); }
        else cp_wait0();
        __syncthreads();
        #pragma unroll
        for (int kk = 0; kk < 32; kk += 16) {
            int col = kk + (lane & 3) * 2;
            uint32_t a[4][4], bf[4][2];
            #pragma unroll
            for (int mi = 0; mi < 4; mi++) {
                int row = wm * 64 + mi * 16 + (lane >> 2);
                a[mi][0] = *(const uint32_t*)&As[s][row * 40 + col];
                a[mi][1] = *(const uint32_t*)&As[s][(row + 8) * 40 + col];
                a[mi][2] = *(const uint32_t*)&As[s][row * 40 + col + 8];
                a[mi][3] = *(const uint32_t*)&As[s][(row + 8) * 40 + col + 8];
            }
            #pragma unroll
            for (int ni = 0; ni < 4; ni++) {
                int n = wn * 32 + ni * 8 + (lane >> 2);
                bf[ni][0] = *(const uint32_t*)&Bs[s][n * 40 + col];
                bf[ni][1] = *(const uint32_t*)&Bs[s][n * 40 + col + 8];
            }
            #pragma unroll
            for (int mi = 0; mi < 4; mi++)
                #pragma unroll
                for (int ni = 0; ni < 4; ni++)
                    mma16816(acc[mi][ni], a[mi], bf[ni]);
        }
        __syncthreads();
    }

    #pragma unroll
    for (int mi = 0; mi < 4; mi++) {
        #pragma unroll
        for (int ni = 0; ni < 4; ni++) {
            int m = m0 + wm * 64 + mi * 16 + (lane >> 2);
            int n = n0 + wn * 32 + ni * 8 + (lane & 3) * 2;
            if (n < LT) {
                g_em[(size_t)m * LT + n]       = acc[mi][ni][0] + fcb[n];
                g_em[(size_t)(m + 8) * LT + n] = acc[mi][ni][2] + fcb[n];
            }
            if (n + 1 < LT) {
                g_em[(size_t)m * LT + n + 1]       = acc[mi][ni][1] + fcb[n + 1];
                g_em[(size_t)(m + 8) * LT + n + 1] = acc[mi][ni][3] + fcb[n + 1];
            }
        }
    }
}

// Persistent fused bidirectional LSTM. 128 CTAs: dir = blk>>6, 8 h-channels each.
// x-projection fused (computed pre-barrier into the same accumulators);
// x prefetched one step ahead; c state in registers.
__global__ void __launch_bounds__(256, 1) k_lstm() {
    extern __shared__ char smem[];
    __nv_bfloat16* whh_s = (__nv_bfloat16*)smem;               // 32 x 520
    __nv_bfloat16* wih_s = whh_s + 32 * 520;                   // 32 x 520
    __nv_bfloat16* hp_s  = wih_s + 32 * 520;                   // 64 x 520
    __nv_bfloat16* xs    = hp_s + 64 * 520;                    // 64 x 520
    float* gates_s = (float*)(xs + 64 * 520);                  // 64 x 32
    float* bias_s  = gates_s + 64 * 32;                        // 32

    int tid = threadIdx.x, lane = tid & 31, warp = tid >> 5;
    int dir = blockIdx.x >> 6, cta = blockIdx.x & 63, c0 = cta * 8;
    int wm = warp & 3, wn = warp >> 2;                         // 4(M) x 2(N)

    // load weight slices (32 gate rows: r = gate*512 + c0 + ch)
    for (int i = tid; i < 32 * 512; i += 256) {
        int j = i >> 9, k = i & 511;
        int r = ((j >> 3) << 9) + c0 + (j & 7);
        whh_s[j * 520 + k] = g_Whh[((size_t)dir * NG + r) * HD + k];
        wih_s[j * 520 + k] = g_Wih[((size_t)dir * NG + r) * EMBD + k];
    }
    if (tid < 32) bias_s[tid] = g_bias[dir * NG + ((tid >> 3) << 9) + c0 + (tid & 7)];

    float2 creg = make_float2(0.f, 0.f);
    int pb = tid >> 2, pc = (tid & 3) * 2;                     // pointwise ownership

    auto loadX = [&](int t) {
        for (int i = tid; i < 4096; i += 256) {
            int b = i >> 6, seg = i & 63;
            cp_async16(&xs[b * 520 + seg * 8],
                       g_A + ((size_t)t * 64 + b) * EMBD + seg * 8);
        }
    };
    auto loadH = [&](int t) {
        for (int i = tid; i < 4096; i += 256) {
            int b = i >> 6, seg = i & 63;
            cp_async16(&hp_s[b * 520 + seg * 8],
                       g_H + ((size_t)dir * MR + (size_t)t * 64 + b) * HD + seg * 8);
        }
    };

    loadX(dir ? TLEN - 1 : 0);
    cp_commit();

    for (int s = 0; s < TLEN; s++) {
        int t = dir ? (TLEN - 1 - s) : s;
        cp_wait0();
        __syncthreads();                         // xs(t) ready; weights ready (s==0)

        float acc[2][4] = {{0, 0, 0, 0}, {0, 0, 0, 0}};
        mat64x32(xs, wih_s, acc, lane, wm, wn);  // x-projection, pre-barrier
        __syncthreads();                         // all warps done reading xs

        if (s > 0) {
            if (lane == 0) { while (ld_acq(&g_cnt[dir]) < s * 64) { } }
            __syncwarp();
            loadH(dir ? t + 1 : t - 1);
            cp_commit();                         // group A (h)
        }
        if (s + 1 < TLEN) { loadX(dir ? t - 1 : t + 1); cp_commit(); }  // group B (x)

        if (s > 0) {
            if (s + 1 < TLEN) cp_wait1(); else cp_wait0();   // h ready, x may fly
            __syncthreads();
            mat64x32(hp_s, whh_s, acc, lane, wm, wn);
        }

        // gates = acc + bias
        #pragma unroll
        for (int f = 0; f < 2; f++) {
            int r0 = wm * 16 + (lane >> 2);
            int n  = wn * 16 + f * 8 + (lane & 3) * 2;
            float b0 = bias_s[n], b1 = bias_s[n + 1];
            gates_s[r0 * 32 + n]           = acc[f][0] + b0;
            gates_s[r0 * 32 + n + 1]       = acc[f][1] + b1;
            gates_s[(r0 + 8) * 32 + n]     = acc[f][2] + b0;
            gates_s[(r0 + 8) * 32 + n + 1] = acc[f][3] + b1;
        }
        __syncthreads();
        {
            float gi0 = gates_s[pb * 32 + pc],      gi1 = gates_s[pb * 32 + pc + 1];
            float gf0 = gates_s[pb * 32 + pc + 8],  gf1 = gates_s[pb * 32 + pc + 9];
            float gg0 = gates_s[pb * 32 + pc + 16], gg1 = gates_s[pb * 32 + pc + 17];
            float go0 = gates_s[pb * 32 + pc + 24], go1 = gates_s[pb * 32 + pc + 25];
            creg.x = sig_f(gf0) * creg.x + sig_f(gi0) * tanh_f(gg0);
            creg.y = sig_f(gf1) * creg.y + sig_f(gi1) * tanh_f(gg1);
            float h0 = sig_f(go0) * tanh_f(creg.x);
            float h1 = sig_f(go1) * tanh_f(creg.y);
            __nv_bfloat162 hv = __float22bfloat162_rn(make_float2(h0, h1));
            *(__nv_bfloat162*)(g_H + ((size_t)dir * MR + (size_t)t * 64 + pb) * HD + c0 + pc) = hv;
        }
        __syncthreads();
        if (tid == 0) { __threadfence(); red_add(&g_cnt[dir], 1); }
    }
}

// CRF forward: exp-trick logsumexp, 256 threads per sequence.
__global__ void __launch_bounds__(256) k_crf(const float* strans, const float* etrans,
                                             const float* trans, const int* tags) {
    __shared__ float Et[48 * 49];
    __shared__ float alpha[48];
    __shared__ float p[48];
    __shared__ float part[4 * 48];
    __shared__ float red[256];
    __shared__ float sm_m;
    int b = blockIdx.x, tid = threadIdx.x;
    for (int i = tid; i < 2304; i += 256) {
        int r = i / 48, c = i - r * 48;
        Et[c * 49 + r] = __expf(trans[i]);
    }
    float num = 0.f;
    for (int t = tid; t < TLEN; t += 256) {
        int tg = tags[b * TLEN + t];
        num += g_em[((size_t)t * 64 + b) * LT + tg];
        num += (t > 0) ? trans[tags[b * TLEN + t - 1] * 48 + tg] : strans[tg];
        if (t == TLEN - 1) num += etrans[tg];
    }
    red[tid] = num; __syncthreads();
    for (int o = 128; o > 0; o >>= 1) { if (tid < o) red[tid] += red[tid + o]; __syncthreads(); }
    num = red[0];
    if (tid < 48) alpha[tid] = strans[tid] + g_em[(size_t)b * LT + tid];
    __syncthreads();
    for (int t = 1; t < TLEN; t++) {
        if (tid < 32) {
            float v = alpha[tid];
            if (tid < 16) v = fmaxf(v, alpha[tid + 32]);
            #pragma unroll
            for (int o = 16; o > 0; o >>= 1) v = fmaxf(v, __shfl_xor_sync(0xffffffffu, v, o));
            if (tid == 0) sm_m = v;
        }
        __syncthreads();
        if (tid < 48) p[tid] = __expf(alpha[tid] - sm_m);
        __syncthreads();
        int q = tid >> 6, j = tid & 63;
        if (j < 48) {
            float s = 0.f;
            #pragma unroll
            for (int u = 0; u < 12; u++) { int i = q * 12 + u; s += p[i] * Et[j * 49 + i]; }
            part[q * 48 + j] = s;
        }
        __syncthreads();
        if (tid < 48) {
            float s = part[tid] + part[48 + tid] + part[96 + tid] + part[144 + tid];
            alpha[tid] = g_em[((size_t)t * 64 + b) * LT + tid] + sm_m + __logf(s);
        }
        __syncthreads();
    }
    float v = (tid < 48) ? alpha[tid] + etrans[tid] : -1e30f;
    red[tid] = v; __syncthreads();
    for (int o = 128; o > 0; o >>= 1) { if (tid < o) red[tid] = fmaxf(red[tid], red[tid + o]); __syncthreads(); }
    float mx = red[0]; __syncthreads();
    red[tid] = (tid < 48) ? __expf(v - mx) : 0.f; __syncthreads();
    for (int o = 128; o > 0; o >>= 1) { if (tid < o) red[tid] += red[tid + o]; __syncthreads(); }
    if (tid == 0) g_llh[b] = num - (mx + __logf(red[0]));
}

__global__ void k_fin(float* out) {
    __shared__ float red[64];
    red[threadIdx.x] = g_llh[threadIdx.x]; __syncthreads();
    for (int o = 32; o > 0; o >>= 1) {
        if (threadIdx.x < o) red[threadIdx.x] += red[threadIdx.x + o];
        __syncthreads();
    }
    if (threadIdx.x == 0) out[0] = -red[0] / 64.f;
}

// ---------------- launch -----------------------------------------------------
extern "C" void kernel_launch(void* const* d_in, const int* in_sizes, int n_in,
                              void* d_out, int out_size) {
    const float* emb    = (const float*)d_in[0];
    const float* wihf   = (const float*)d_in[1];
    const float* whhf   = (const float*)d_in[2];
    const float* bihf   = (const float*)d_in[3];
    const float* bhhf   = (const float*)d_in[4];
    const float* wihb   = (const float*)d_in[5];
    const float* whhb   = (const float*)d_in[6];
    const float* bihb   = (const float*)d_in[7];
    const float* bhhb   = (const float*)d_in[8];
    const float* fcw    = (const float*)d_in[9];
    const float* fcb    = (const float*)d_in[10];
    const float* strans = (const float*)d_in[11];
    const float* etrans = (const float*)d_in[12];
    const float* trans  = (const float*)d_in[13];
    const int*   x      = (const int*)d_in[14];
    const int*   tags   = (const int*)d_in[15];
    float* out = (float*)d_out;

    const int lstm_smem = 2 * (32 * 520 * 2) + 2 * (64 * 520 * 2) + 64 * 32 * 4 + 32 * 4;
    cudaFuncSetAttribute(k_lstm, cudaFuncAttributeMaxDynamicSharedMemorySize, lstm_smem);

    k_reset<<<1, 32>>>();
    k_prep<<<2048, 256>>>(wihf, whhf, bihf, bhhf, wihb, whhb, bihb, bhhb, fcw);
    k_gather<<<8192, 256>>>(emb, x);
    k_lstm<<<128, 256, lstm_smem>>>();
    k_gemm<<<dim3(1, 256), 256>>>(fcb);
    k_crf<<<64, 256>>>(strans, etrans, trans, tags);
    k_fin<<<1, 64>>>(out);
}